// round 1
// baseline (speedup 1.0000x reference)
#include <cuda_runtime.h>

#define NN   4096
#define NE   32768
#define ET   (NE + NN)        // edges + self loops = 36864
#define F_IN 128
#define HEADS 8
#define HID  512
#define D1   (HEADS * HID)    // 4096

// ---------------- scratch (device globals; no allocation allowed) ----------
__device__ float g_h1[(size_t)NN * D1];     // 64 MB
__device__ float g_out1[(size_t)NN * D1];   // 64 MB
__device__ float g_h2[NN * HID];            // 8 MB
__device__ float g_out2[NN * HID];          // 8 MB
__device__ float g_as1[NN * HEADS], g_ad1[NN * HEADS];
__device__ float g_e1[ET * HEADS];
__device__ float g_as2[NN], g_ad2[NN];
__device__ float g_e2[ET];
__device__ int   g_deg[NN], g_cur[NN], g_off[NN + 1];
__device__ int   g_eid[ET], g_esrc[ET];
__device__ int   g_is64;
__device__ float g_g1[512 * 512], g_g2[512 * 128];

// ---------------- helpers ---------------------------------------------------
__device__ __forceinline__ float warpSum(float v) {
    #pragma unroll
    for (int o = 16; o; o >>= 1) v += __shfl_xor_sync(0xffffffffu, v, o);
    return v;
}
__device__ __forceinline__ float warpMax(float v) {
    #pragma unroll
    for (int o = 16; o; o >>= 1) v = fmaxf(v, __shfl_xor_sync(0xffffffffu, v, o));
    return v;
}
// edge_index may be int64 or int32 depending on JAX x64 config; g_is64 set at runtime.
__device__ __forceinline__ int eload(const int* ei, int pos) {
    return g_is64 ? ei[2 * pos] : ei[pos];
}
__device__ __forceinline__ int esrc_of(const int* ei, int e) {
    return (e < NE) ? eload(ei, e) : (e - NE);
}
__device__ __forceinline__ int edst_of(const int* ei, int e) {
    return (e < NE) ? eload(ei, NE + e) : (e - NE);
}

// ---------------- dtype sniff + CSR build ----------------------------------
__global__ void detect_kernel(const int* __restrict__ ei) {
    if (threadIdx.x == 0) {
        int all0 = 1;
        for (int k = 1; k < 64; k += 2) all0 &= (ei[k] == 0);
        g_is64 = all0;   // int64: high words of small nonneg values are 0
    }
}

__global__ void init_kernel() {
    int i = blockIdx.x * blockDim.x + threadIdx.x;
    if (i < NN) { g_deg[i] = 0; g_cur[i] = 0; }
}

__global__ void count_kernel(const int* __restrict__ ei) {
    int e = blockIdx.x * blockDim.x + threadIdx.x;
    if (e >= ET) return;
    atomicAdd(&g_deg[edst_of(ei, e)], 1);
}

__global__ void scan_kernel() {   // 1 block, 1024 threads, 4 elems/thread
    __shared__ int ws[32];
    int t = threadIdx.x, lane = t & 31, wid = t >> 5;
    int a0 = g_deg[4 * t + 0], a1 = g_deg[4 * t + 1];
    int a2 = g_deg[4 * t + 2], a3 = g_deg[4 * t + 3];
    int tsum = a0 + a1 + a2 + a3;
    int x = tsum;
    #pragma unroll
    for (int o = 1; o < 32; o <<= 1) {
        int y = __shfl_up_sync(0xffffffffu, x, o);
        if (lane >= o) x += y;
    }
    if (lane == 31) ws[wid] = x;
    __syncthreads();
    if (wid == 0) {
        int y = ws[lane];
        #pragma unroll
        for (int o = 1; o < 32; o <<= 1) {
            int z = __shfl_up_sync(0xffffffffu, y, o);
            if (lane >= o) y += z;
        }
        ws[lane] = y;
    }
    __syncthreads();
    int base = (wid ? ws[wid - 1] : 0) + (x - tsum);
    g_off[4 * t + 0] = base;
    g_off[4 * t + 1] = base + a0;
    g_off[4 * t + 2] = base + a0 + a1;
    g_off[4 * t + 3] = base + a0 + a1 + a2;
    if (t == 1023) g_off[NN] = base + tsum;
}

__global__ void fill_kernel(const int* __restrict__ ei) {
    int e = blockIdx.x * blockDim.x + threadIdx.x;
    if (e >= ET) return;
    int s = esrc_of(ei, e), d = edst_of(ei, e);
    int p = g_off[d] + atomicAdd(&g_cur[d], 1);
    g_eid[p] = e;
    g_esrc[p] = s;
}

// ---------------- generic tiled fp32 SGEMM ----------------------------------
// A[M,K] row-major, B[K,N] row-major, C[M,N]. Assumes K % BK == 0, K % 4 == 0.
template<int BM, int BN, int BK, int TM, int TN>
__global__ __launch_bounds__((BM / TM) * (BN / TN))
void sgemm(const float* __restrict__ A, const float* __restrict__ B,
           const float* __restrict__ bias, float* __restrict__ C,
           int M, int N, int K, int relu)
{
    constexpr int THREADS = (BM / TM) * (BN / TN);
    __shared__ float As[BK][BM];
    __shared__ float Bs[BK][BN];
    const int tid = threadIdx.x;
    const int row0 = blockIdx.y * BM, col0 = blockIdx.x * BN;
    const int tr = (tid / (BN / TN)) * TM;
    const int tc = (tid % (BN / TN)) * TN;
    const bool vb = (N % 4) == 0;

    float acc[TM][TN];
    #pragma unroll
    for (int i = 0; i < TM; i++)
        #pragma unroll
        for (int j = 0; j < TN; j++) acc[i][j] = 0.f;

    for (int k0 = 0; k0 < K; k0 += BK) {
        // A tile (vectorized along K, transposed into As)
        #pragma unroll 4
        for (int i = tid * 4; i < BM * BK; i += THREADS * 4) {
            int r = i / BK, c = i % BK;
            int gr = row0 + r, gc = k0 + c;
            float4 v = make_float4(0.f, 0.f, 0.f, 0.f);
            if (gr < M) v = *reinterpret_cast<const float4*>(A + (size_t)gr * K + gc);
            As[c + 0][r] = v.x; As[c + 1][r] = v.y;
            As[c + 2][r] = v.z; As[c + 3][r] = v.w;
        }
        // B tile
        #pragma unroll 4
        for (int i = tid * 4; i < BK * BN; i += THREADS * 4) {
            int r = i / BN, c = i % BN;
            int gr = k0 + r, gc = col0 + c;
            float vv0 = 0.f, vv1 = 0.f, vv2 = 0.f, vv3 = 0.f;
            if (vb && gc + 3 < N) {
                float4 v = *reinterpret_cast<const float4*>(B + (size_t)gr * N + gc);
                vv0 = v.x; vv1 = v.y; vv2 = v.z; vv3 = v.w;
            } else {
                if (gc + 0 < N) vv0 = B[(size_t)gr * N + gc + 0];
                if (gc + 1 < N) vv1 = B[(size_t)gr * N + gc + 1];
                if (gc + 2 < N) vv2 = B[(size_t)gr * N + gc + 2];
                if (gc + 3 < N) vv3 = B[(size_t)gr * N + gc + 3];
            }
            Bs[r][c + 0] = vv0; Bs[r][c + 1] = vv1;
            Bs[r][c + 2] = vv2; Bs[r][c + 3] = vv3;
        }
        __syncthreads();
        #pragma unroll
        for (int kk = 0; kk < BK; kk++) {
            float ar[TM], br[TN];
            #pragma unroll
            for (int i = 0; i < TM; i++) ar[i] = As[kk][tr + i];
            #pragma unroll
            for (int j = 0; j < TN; j++) br[j] = Bs[kk][tc + j];
            #pragma unroll
            for (int i = 0; i < TM; i++)
                #pragma unroll
                for (int j = 0; j < TN; j++) acc[i][j] += ar[i] * br[j];
        }
        __syncthreads();
    }
    #pragma unroll
    for (int i = 0; i < TM; i++) {
        int r = row0 + tr + i;
        if (r >= M) continue;
        #pragma unroll
        for (int j = 0; j < TN; j++) {
            int c = col0 + tc + j;
            if (c >= N) continue;
            float v = acc[i][j] + (bias ? bias[c] : 0.f);
            if (relu) v = fmaxf(v, 0.f);
            C[(size_t)r * N + c] = v;
        }
    }
}

// ---------------- GAT layer 1 (8 heads x 512) -------------------------------
__global__ void alpha1_kernel(const float* __restrict__ asrc,
                              const float* __restrict__ adst) {
    int n = blockIdx.x;
    int w = threadIdx.x >> 5, lane = threadIdx.x & 31;   // w = head
    const float* hrow = g_h1 + (size_t)n * D1 + w * HID;
    float s1 = 0.f, s2 = 0.f;
    for (int c = lane; c < HID; c += 32) {
        float v = hrow[c];
        s1 += v * asrc[w * HID + c];
        s2 += v * adst[w * HID + c];
    }
    s1 = warpSum(s1); s2 = warpSum(s2);
    if (lane == 0) { g_as1[n * HEADS + w] = s1; g_ad1[n * HEADS + w] = s2; }
}

__global__ void edge1_kernel(const int* __restrict__ ei) {
    int idx = blockIdx.x * blockDim.x + threadIdx.x;
    if (idx >= ET * HEADS) return;
    int e = idx >> 3, h = idx & 7;
    int s = esrc_of(ei, e), d = edst_of(ei, e);
    float v = g_as1[s * HEADS + h] + g_ad1[d * HEADS + h];
    g_e1[idx] = v > 0.f ? v : 0.2f * v;
}

__global__ void norm1_kernel() {   // warp per (node, head)
    int n = blockIdx.x;
    int w = threadIdx.x >> 5, lane = threadIdx.x & 31;
    int beg = g_off[n], end = g_off[n + 1];
    float m = -3.4e38f;
    for (int i = beg + lane; i < end; i += 32)
        m = fmaxf(m, g_e1[g_eid[i] * HEADS + w]);
    m = warpMax(m);
    float s = 0.f;
    for (int i = beg + lane; i < end; i += 32)
        s += expf(g_e1[g_eid[i] * HEADS + w] - m);
    s = warpSum(s);
    float inv = 1.f / s;
    for (int i = beg + lane; i < end; i += 32) {
        int idx = g_eid[i] * HEADS + w;
        g_e1[idx] = expf(g_e1[idx] - m) * inv;
    }
}

__global__ void agg1_kernel(const float* __restrict__ b1) {
    int n = blockIdx.x;
    int t = threadIdx.x;                 // 256 threads, 16 channels each
    int c0 = t * 16;
    int head = c0 >> 9;                  // uniform per warp
    int beg = g_off[n], end = g_off[n + 1];
    float acc[16];
    #pragma unroll
    for (int j = 0; j < 16; j++) acc[j] = 0.f;
    for (int i = beg; i < end; i++) {
        int e = g_eid[i], s = g_esrc[i];
        float al = g_e1[e * HEADS + head];
        const float4* hs = reinterpret_cast<const float4*>(g_h1 + (size_t)s * D1 + c0);
        #pragma unroll
        for (int j = 0; j < 4; j++) {
            float4 v = hs[j];
            acc[4 * j + 0] += v.x * al; acc[4 * j + 1] += v.y * al;
            acc[4 * j + 2] += v.z * al; acc[4 * j + 3] += v.w * al;
        }
    }
    float* o = g_out1 + (size_t)n * D1 + c0;
    #pragma unroll
    for (int j = 0; j < 16; j++) {
        float v = acc[j] + b1[c0 + j];
        o[j] = fmaxf(v, 0.f);           // relu after GAT1
    }
}

// ---------------- GAT layer 2 (1 head x 512) --------------------------------
__global__ void alpha2_kernel(const float* __restrict__ asrc,
                              const float* __restrict__ adst) {
    int n = blockIdx.x * 8 + (threadIdx.x >> 5);
    int lane = threadIdx.x & 31;
    const float* hrow = g_h2 + (size_t)n * HID;
    float s1 = 0.f, s2 = 0.f;
    for (int c = lane; c < HID; c += 32) {
        float v = hrow[c];
        s1 += v * asrc[c];
        s2 += v * adst[c];
    }
    s1 = warpSum(s1); s2 = warpSum(s2);
    if (lane == 0) { g_as2[n] = s1; g_ad2[n] = s2; }
}

__global__ void edge2_kernel(const int* __restrict__ ei) {
    int e = blockIdx.x * blockDim.x + threadIdx.x;
    if (e >= ET) return;
    int s = esrc_of(ei, e), d = edst_of(ei, e);
    float v = g_as2[s] + g_ad2[d];
    g_e2[e] = v > 0.f ? v : 0.2f * v;
}

__global__ void norm2_kernel() {   // warp per node
    int n = blockIdx.x * 8 + (threadIdx.x >> 5);
    int lane = threadIdx.x & 31;
    int beg = g_off[n], end = g_off[n + 1];
    float m = -3.4e38f;
    for (int i = beg + lane; i < end; i += 32)
        m = fmaxf(m, g_e2[g_eid[i]]);
    m = warpMax(m);
    float s = 0.f;
    for (int i = beg + lane; i < end; i += 32)
        s += expf(g_e2[g_eid[i]] - m);
    s = warpSum(s);
    float inv = 1.f / s;
    for (int i = beg + lane; i < end; i += 32) {
        int e = g_eid[i];
        g_e2[e] = expf(g_e2[e] - m) * inv;
    }
}

__global__ void agg2_kernel(const float* __restrict__ b2) {
    int n = blockIdx.x;
    int t = threadIdx.x;                 // 128 threads, 4 channels each
    int c0 = t * 4;
    int beg = g_off[n], end = g_off[n + 1];
    float a0 = 0.f, a1 = 0.f, a2 = 0.f, a3 = 0.f;
    for (int i = beg; i < end; i++) {
        int e = g_eid[i], s = g_esrc[i];
        float al = g_e2[e];
        float4 v = *reinterpret_cast<const float4*>(g_h2 + (size_t)s * HID + c0);
        a0 += v.x * al; a1 += v.y * al; a2 += v.z * al; a3 += v.w * al;
    }
    float* o = g_out2 + (size_t)n * HID + c0;
    o[0] = fmaxf(a0 + b2[c0 + 0], 0.f);
    o[1] = fmaxf(a1 + b2[c0 + 1], 0.f);
    o[2] = fmaxf(a2 + b2[c0 + 2], 0.f);
    o[3] = fmaxf(a3 + b2[c0 + 3], 0.f);
}

// ---------------- launch -----------------------------------------------------
extern "C" void kernel_launch(void* const* d_in, const int* in_sizes, int n_in,
                              void* d_out, int out_size) {
    const float* x      = (const float*)d_in[0];
    const int*   ei     = (const int*)d_in[1];     // int32 view; dtype sniffed on device
    const float* W1     = (const float*)d_in[3];
    const float* a_src1 = (const float*)d_in[4];
    const float* a_dst1 = (const float*)d_in[5];
    const float* b1     = (const float*)d_in[6];
    const float* W2     = (const float*)d_in[7];
    const float* a_src2 = (const float*)d_in[8];
    const float* a_dst2 = (const float*)d_in[9];
    const float* b2     = (const float*)d_in[10];
    const float* fc1w   = (const float*)d_in[11];
    const float* fc1b   = (const float*)d_in[12];
    const float* fc2w   = (const float*)d_in[13];
    const float* fc2b   = (const float*)d_in[14];
    const float* fc3w   = (const float*)d_in[15];
    const float* fc3b   = (const float*)d_in[16];
    float* out = (float*)d_out;

    float *h1, *o1, *h2, *o2, *gg1, *gg2;
    cudaGetSymbolAddress((void**)&h1,  g_h1);
    cudaGetSymbolAddress((void**)&o1,  g_out1);
    cudaGetSymbolAddress((void**)&h2,  g_h2);
    cudaGetSymbolAddress((void**)&o2,  g_out2);
    cudaGetSymbolAddress((void**)&gg1, g_g1);
    cudaGetSymbolAddress((void**)&gg2, g_g2);

    // edge dtype + CSR (recomputed every call; deterministic work)
    detect_kernel<<<1, 32>>>(ei);
    init_kernel<<<(NN + 255) / 256, 256>>>();
    count_kernel<<<(ET + 255) / 256, 256>>>(ei);
    scan_kernel<<<1, 1024>>>();
    fill_kernel<<<(ET + 255) / 256, 256>>>(ei);

    // GAT layer 1
    sgemm<128, 128, 8, 8, 8><<<dim3(D1 / 128, NN / 128), 256>>>(
        x, W1, nullptr, h1, NN, D1, F_IN, 0);
    alpha1_kernel<<<NN, 256>>>(a_src1, a_dst1);
    edge1_kernel<<<(ET * HEADS + 255) / 256, 256>>>(ei);
    norm1_kernel<<<NN, 256>>>();
    agg1_kernel<<<NN, 256>>>(b1);

    // GAT layer 2
    sgemm<128, 64, 8, 8, 4><<<dim3(HID / 64, NN / 128), 256>>>(
        o1, W2, nullptr, h2, NN, HID, D1, 0);
    alpha2_kernel<<<NN / 8, 256>>>(a_src2, a_dst2);
    edge2_kernel<<<(ET + 255) / 256, 256>>>(ei);
    norm2_kernel<<<NN / 8, 256>>>();
    agg2_kernel<<<NN, 128>>>(b2);

    // MLP head: g = out2 viewed as [512, 4096]
    sgemm<64, 64, 16, 4, 4><<<dim3(512 / 64, 512 / 64), 256>>>(
        o2, fc1w, fc1b, gg1, 512, 512, D1, 1);
    sgemm<64, 64, 16, 4, 4><<<dim3(128 / 64, 512 / 64), 256>>>(
        gg1, fc2w, fc2b, gg2, 512, 128, 512, 1);
    sgemm<64, 64, 16, 4, 4><<<dim3(1, 512 / 64), 256>>>(
        gg2, fc3w, fc3b, out, 512, 10, 128, 0);
}

// round 2
// speedup vs baseline: 2.3939x; 2.3939x over previous
#include <cuda_runtime.h>
#include <cstdint>

#define NN   4096
#define NE   32768
#define ET   (NE + NN)        // edges + self loops = 36864
#define F_IN 128
#define HEADS 8
#define HID  512
#define D1   (HEADS * HID)    // 4096

// ---------------- scratch (device globals; no allocation allowed) ----------
__device__ float g_h1[(size_t)NN * D1];     // 64 MB
__device__ float g_out1[(size_t)NN * D1];   // 64 MB
__device__ float g_h2[NN * HID];            // 8 MB
__device__ float g_out2[NN * HID];          // 8 MB
__device__ float g_as1[NN * HEADS], g_ad1[NN * HEADS];
__device__ float g_e1[ET * HEADS];
__device__ float g_as2[NN], g_ad2[NN];
__device__ float g_e2[ET];
__device__ int   g_deg[NN], g_cur[NN], g_off[NN + 1];
__device__ int   g_eid[ET], g_esrc[ET];
__device__ int   g_is64;
__device__ float g_g1[512 * 512], g_g2[512 * 128];

// ---------------- helpers ---------------------------------------------------
__device__ __forceinline__ float warpSum(float v) {
    #pragma unroll
    for (int o = 16; o; o >>= 1) v += __shfl_xor_sync(0xffffffffu, v, o);
    return v;
}
__device__ __forceinline__ float warpMax(float v) {
    #pragma unroll
    for (int o = 16; o; o >>= 1) v = fmaxf(v, __shfl_xor_sync(0xffffffffu, v, o));
    return v;
}
__device__ __forceinline__ uint32_t f2tf32(float f) {
    uint32_t o;
    asm("cvt.rna.tf32.f32 %0, %1;" : "=r"(o) : "f"(f));
    return o;
}
// edge_index may be int64 or int32 depending on JAX x64 config; g_is64 set at runtime.
__device__ __forceinline__ int eload(const int* ei, int pos) {
    return g_is64 ? ei[2 * pos] : ei[pos];
}
__device__ __forceinline__ int esrc_of(const int* ei, int e) {
    return (e < NE) ? eload(ei, e) : (e - NE);
}
__device__ __forceinline__ int edst_of(const int* ei, int e) {
    return (e < NE) ? eload(ei, NE + e) : (e - NE);
}

// ---------------- dtype sniff + CSR build ----------------------------------
__global__ void detect_kernel(const int* __restrict__ ei) {
    if (threadIdx.x == 0) {
        int all0 = 1;
        for (int k = 1; k < 64; k += 2) all0 &= (ei[k] == 0);
        g_is64 = all0;   // int64: high words of small nonneg values are 0
    }
}

__global__ void init_kernel() {
    int i = blockIdx.x * blockDim.x + threadIdx.x;
    if (i < NN) { g_deg[i] = 0; g_cur[i] = 0; }
}

__global__ void count_kernel(const int* __restrict__ ei) {
    int e = blockIdx.x * blockDim.x + threadIdx.x;
    if (e >= ET) return;
    atomicAdd(&g_deg[edst_of(ei, e)], 1);
}

__global__ void scan_kernel() {   // 1 block, 1024 threads, 4 elems/thread
    __shared__ int ws[32];
    int t = threadIdx.x, lane = t & 31, wid = t >> 5;
    int a0 = g_deg[4 * t + 0], a1 = g_deg[4 * t + 1];
    int a2 = g_deg[4 * t + 2], a3 = g_deg[4 * t + 3];
    int tsum = a0 + a1 + a2 + a3;
    int x = tsum;
    #pragma unroll
    for (int o = 1; o < 32; o <<= 1) {
        int y = __shfl_up_sync(0xffffffffu, x, o);
        if (lane >= o) x += y;
    }
    if (lane == 31) ws[wid] = x;
    __syncthreads();
    if (wid == 0) {
        int y = ws[lane];
        #pragma unroll
        for (int o = 1; o < 32; o <<= 1) {
            int z = __shfl_up_sync(0xffffffffu, y, o);
            if (lane >= o) y += z;
        }
        ws[lane] = y;
    }
    __syncthreads();
    int base = (wid ? ws[wid - 1] : 0) + (x - tsum);
    g_off[4 * t + 0] = base;
    g_off[4 * t + 1] = base + a0;
    g_off[4 * t + 2] = base + a0 + a1;
    g_off[4 * t + 3] = base + a0 + a1 + a2;
    if (t == 1023) g_off[NN] = base + tsum;
}

__global__ void fill_kernel(const int* __restrict__ ei) {
    int e = blockIdx.x * blockDim.x + threadIdx.x;
    if (e >= ET) return;
    int s = esrc_of(ei, e), d = edst_of(ei, e);
    int p = g_off[d] + atomicAdd(&g_cur[d], 1);
    g_eid[p] = e;
    g_esrc[p] = s;
}

// ---------------- TF32 tensor-core GEMM -------------------------------------
// A[M,K] rm, B[K,N] rm, C[M,N]. Requires M%BM==0, N%BN==0, K%32==0, K%4==0.
template<int BM, int BN, int WM, int WN>
__global__ __launch_bounds__((BM / WM) * (BN / WN) * 32)
void tf32gemm(const float* __restrict__ A, const float* __restrict__ B,
              const float* __restrict__ bias, float* __restrict__ C,
              int M, int N, int K, int relu)
{
    constexpr int BK = 32;
    constexpr int WARPS = (BM / WM) * (BN / WN);
    constexpr int THREADS = WARPS * 32;
    constexpr int MF = WM / 16, NF = WN / 8;
    constexpr int AST = BK + 4;   // 36 -> A-frag LDS conflict-free
    constexpr int BST = BN + 4;   // stride%32==4 -> B-frag max 2-way
    constexpr int ALD = (BM * BK) / (4 * THREADS);
    constexpr int BLD = (BK * BN) / (4 * THREADS);

    __shared__ uint32_t As[BM * AST];
    __shared__ uint32_t Bs[BK * BST];

    const int tid = threadIdx.x;
    const int wid = tid >> 5, lane = tid & 31;
    const int wm = wid / (BN / WN), wn = wid % (BN / WN);
    const int g = lane >> 2, tg = lane & 3;
    const int row0 = blockIdx.y * BM, col0 = blockIdx.x * BN;

    float acc[MF][NF][4];
    #pragma unroll
    for (int i = 0; i < MF; i++)
        #pragma unroll
        for (int j = 0; j < NF; j++)
            #pragma unroll
            for (int q = 0; q < 4; q++) acc[i][j][q] = 0.f;

    float4 pa[ALD], pb[BLD];

    auto ldAB = [&](int k0) {
        #pragma unroll
        for (int j = 0; j < ALD; j++) {
            int fid = tid + j * THREADS;
            int r = fid / (BK / 4), c4 = fid % (BK / 4);
            pa[j] = *reinterpret_cast<const float4*>(A + (size_t)(row0 + r) * K + k0 + c4 * 4);
        }
        #pragma unroll
        for (int j = 0; j < BLD; j++) {
            int fid = tid + j * THREADS;
            int r = fid / (BN / 4), c4 = fid % (BN / 4);
            pb[j] = *reinterpret_cast<const float4*>(B + (size_t)(k0 + r) * N + col0 + c4 * 4);
        }
    };
    auto stash = [&]() {
        #pragma unroll
        for (int j = 0; j < ALD; j++) {
            int fid = tid + j * THREADS;
            int r = fid / (BK / 4), c4 = fid % (BK / 4);
            uint4 v;
            v.x = f2tf32(pa[j].x); v.y = f2tf32(pa[j].y);
            v.z = f2tf32(pa[j].z); v.w = f2tf32(pa[j].w);
            *reinterpret_cast<uint4*>(&As[r * AST + c4 * 4]) = v;
        }
        #pragma unroll
        for (int j = 0; j < BLD; j++) {
            int fid = tid + j * THREADS;
            int r = fid / (BN / 4), c4 = fid % (BN / 4);
            uint4 v;
            v.x = f2tf32(pb[j].x); v.y = f2tf32(pb[j].y);
            v.z = f2tf32(pb[j].z); v.w = f2tf32(pb[j].w);
            *reinterpret_cast<uint4*>(&Bs[r * BST + c4 * 4]) = v;
        }
    };

    ldAB(0);
    stash();
    __syncthreads();

    const int niter = K / BK;
    for (int it = 0; it < niter; ++it) {
        if (it + 1 < niter) ldAB((it + 1) * BK);   // prefetch to regs

        #pragma unroll
        for (int kk = 0; kk < 4; kk++) {
            uint32_t af[MF][4], bf[NF][2];
            #pragma unroll
            for (int mf = 0; mf < MF; mf++) {
                int r = wm * WM + mf * 16;
                af[mf][0] = As[(r + g    ) * AST + kk * 8 + tg    ];
                af[mf][1] = As[(r + g + 8) * AST + kk * 8 + tg    ];
                af[mf][2] = As[(r + g    ) * AST + kk * 8 + tg + 4];
                af[mf][3] = As[(r + g + 8) * AST + kk * 8 + tg + 4];
            }
            #pragma unroll
            for (int nf = 0; nf < NF; nf++) {
                int c = wn * WN + nf * 8 + g;
                bf[nf][0] = Bs[(kk * 8 + tg    ) * BST + c];
                bf[nf][1] = Bs[(kk * 8 + tg + 4) * BST + c];
            }
            #pragma unroll
            for (int mf = 0; mf < MF; mf++)
                #pragma unroll
                for (int nf = 0; nf < NF; nf++)
                    asm volatile(
                        "mma.sync.aligned.m16n8k8.row.col.f32.tf32.tf32.f32 "
                        "{%0,%1,%2,%3},{%4,%5,%6,%7},{%8,%9},{%0,%1,%2,%3};\n"
                        : "+f"(acc[mf][nf][0]), "+f"(acc[mf][nf][1]),
                          "+f"(acc[mf][nf][2]), "+f"(acc[mf][nf][3])
                        : "r"(af[mf][0]), "r"(af[mf][1]),
                          "r"(af[mf][2]), "r"(af[mf][3]),
                          "r"(bf[nf][0]), "r"(bf[nf][1]));
        }
        __syncthreads();
        if (it + 1 < niter) { stash(); __syncthreads(); }
    }

    // epilogue
    #pragma unroll
    for (int mf = 0; mf < MF; mf++) {
        int r = row0 + wm * WM + mf * 16 + g;
        #pragma unroll
        for (int nf = 0; nf < NF; nf++) {
            int c = col0 + wn * WN + nf * 8 + tg * 2;
            float b0v = bias ? bias[c] : 0.f;
            float b1v = bias ? bias[c + 1] : 0.f;
            float v0 = acc[mf][nf][0] + b0v, v1 = acc[mf][nf][1] + b1v;
            float v2 = acc[mf][nf][2] + b0v, v3 = acc[mf][nf][3] + b1v;
            if (relu) {
                v0 = fmaxf(v0, 0.f); v1 = fmaxf(v1, 0.f);
                v2 = fmaxf(v2, 0.f); v3 = fmaxf(v3, 0.f);
            }
            *reinterpret_cast<float2*>(C + (size_t)r * N + c) = make_float2(v0, v1);
            *reinterpret_cast<float2*>(C + (size_t)(r + 8) * N + c) = make_float2(v2, v3);
        }
    }
}

// ---------------- fp32 tiled SGEMM (small tail GEMM only) --------------------
template<int BM, int BN, int BK, int TM, int TN>
__global__ __launch_bounds__((BM / TM) * (BN / TN))
void sgemm(const float* __restrict__ A, const float* __restrict__ B,
           const float* __restrict__ bias, float* __restrict__ C,
           int M, int N, int K, int relu)
{
    constexpr int THREADS = (BM / TM) * (BN / TN);
    __shared__ float As[BK][BM];
    __shared__ float Bs[BK][BN];
    const int tid = threadIdx.x;
    const int row0 = blockIdx.y * BM, col0 = blockIdx.x * BN;
    const int tr = (tid / (BN / TN)) * TM;
    const int tc = (tid % (BN / TN)) * TN;
    const bool vb = (N % 4) == 0;

    float acc[TM][TN];
    #pragma unroll
    for (int i = 0; i < TM; i++)
        #pragma unroll
        for (int j = 0; j < TN; j++) acc[i][j] = 0.f;

    for (int k0 = 0; k0 < K; k0 += BK) {
        #pragma unroll 4
        for (int i = tid * 4; i < BM * BK; i += THREADS * 4) {
            int r = i / BK, c = i % BK;
            int gr = row0 + r, gc = k0 + c;
            float4 v = make_float4(0.f, 0.f, 0.f, 0.f);
            if (gr < M) v = *reinterpret_cast<const float4*>(A + (size_t)gr * K + gc);
            As[c + 0][r] = v.x; As[c + 1][r] = v.y;
            As[c + 2][r] = v.z; As[c + 3][r] = v.w;
        }
        #pragma unroll 4
        for (int i = tid * 4; i < BK * BN; i += THREADS * 4) {
            int r = i / BN, c = i % BN;
            int gr = k0 + r, gc = col0 + c;
            float vv0 = 0.f, vv1 = 0.f, vv2 = 0.f, vv3 = 0.f;
            if (vb && gc + 3 < N) {
                float4 v = *reinterpret_cast<const float4*>(B + (size_t)gr * N + gc);
                vv0 = v.x; vv1 = v.y; vv2 = v.z; vv3 = v.w;
            } else {
                if (gc + 0 < N) vv0 = B[(size_t)gr * N + gc + 0];
                if (gc + 1 < N) vv1 = B[(size_t)gr * N + gc + 1];
                if (gc + 2 < N) vv2 = B[(size_t)gr * N + gc + 2];
                if (gc + 3 < N) vv3 = B[(size_t)gr * N + gc + 3];
            }
            Bs[r][c + 0] = vv0; Bs[r][c + 1] = vv1;
            Bs[r][c + 2] = vv2; Bs[r][c + 3] = vv3;
        }
        __syncthreads();
        #pragma unroll
        for (int kk = 0; kk < BK; kk++) {
            float ar[TM], br[TN];
            #pragma unroll
            for (int i = 0; i < TM; i++) ar[i] = As[kk][tr + i];
            #pragma unroll
            for (int j = 0; j < TN; j++) br[j] = Bs[kk][tc + j];
            #pragma unroll
            for (int i = 0; i < TM; i++)
                #pragma unroll
                for (int j = 0; j < TN; j++) acc[i][j] += ar[i] * br[j];
        }
        __syncthreads();
    }
    #pragma unroll
    for (int i = 0; i < TM; i++) {
        int r = row0 + tr + i;
        if (r >= M) continue;
        #pragma unroll
        for (int j = 0; j < TN; j++) {
            int c = col0 + tc + j;
            if (c >= N) continue;
            float v = acc[i][j] + (bias ? bias[c] : 0.f);
            if (relu) v = fmaxf(v, 0.f);
            C[(size_t)r * N + c] = v;
        }
    }
}

// ---------------- GAT layer 1 (8 heads x 512) -------------------------------
__global__ void alpha1_kernel(const float* __restrict__ asrc,
                              const float* __restrict__ adst) {
    int n = blockIdx.x;
    int w = threadIdx.x >> 5, lane = threadIdx.x & 31;   // w = head
    const float* hrow = g_h1 + (size_t)n * D1 + w * HID;
    float s1 = 0.f, s2 = 0.f;
    for (int c = lane; c < HID; c += 32) {
        float v = hrow[c];
        s1 += v * asrc[w * HID + c];
        s2 += v * adst[w * HID + c];
    }
    s1 = warpSum(s1); s2 = warpSum(s2);
    if (lane == 0) { g_as1[n * HEADS + w] = s1; g_ad1[n * HEADS + w] = s2; }
}

__global__ void edge1_kernel(const int* __restrict__ ei) {
    int idx = blockIdx.x * blockDim.x + threadIdx.x;
    if (idx >= ET * HEADS) return;
    int e = idx >> 3, h = idx & 7;
    int s = esrc_of(ei, e), d = edst_of(ei, e);
    float v = g_as1[s * HEADS + h] + g_ad1[d * HEADS + h];
    g_e1[idx] = v > 0.f ? v : 0.2f * v;
}

__global__ void norm1_kernel() {   // warp per (node, head)
    int n = blockIdx.x;
    int w = threadIdx.x >> 5, lane = threadIdx.x & 31;
    int beg = g_off[n], end = g_off[n + 1];
    float m = -3.4e38f;
    for (int i = beg + lane; i < end; i += 32)
        m = fmaxf(m, g_e1[g_eid[i] * HEADS + w]);
    m = warpMax(m);
    float s = 0.f;
    for (int i = beg + lane; i < end; i += 32)
        s += expf(g_e1[g_eid[i] * HEADS + w] - m);
    s = warpSum(s);
    float inv = 1.f / s;
    for (int i = beg + lane; i < end; i += 32) {
        int idx = g_eid[i] * HEADS + w;
        g_e1[idx] = expf(g_e1[idx] - m) * inv;
    }
}

__global__ void agg1_kernel(const float* __restrict__ b1) {
    int n = blockIdx.x;
    int t = threadIdx.x;                 // 256 threads, 16 channels each
    int c0 = t * 16;
    int head = c0 >> 9;                  // uniform per warp
    int beg = g_off[n], end = g_off[n + 1];
    float acc[16];
    #pragma unroll
    for (int j = 0; j < 16; j++) acc[j] = 0.f;
    for (int i = beg; i < end; i++) {
        int e = g_eid[i], s = g_esrc[i];
        float al = g_e1[e * HEADS + head];
        const float4* hs = reinterpret_cast<const float4*>(g_h1 + (size_t)s * D1 + c0);
        #pragma unroll
        for (int j = 0; j < 4; j++) {
            float4 v = hs[j];
            acc[4 * j + 0] += v.x * al; acc[4 * j + 1] += v.y * al;
            acc[4 * j + 2] += v.z * al; acc[4 * j + 3] += v.w * al;
        }
    }
    float* o = g_out1 + (size_t)n * D1 + c0;
    #pragma unroll
    for (int j = 0; j < 16; j++) {
        float v = acc[j] + b1[c0 + j];
        o[j] = fmaxf(v, 0.f);           // relu after GAT1
    }
}

// ---------------- GAT layer 2 (1 head x 512) --------------------------------
__global__ void alpha2_kernel(const float* __restrict__ asrc,
                              const float* __restrict__ adst) {
    int n = blockIdx.x * 8 + (threadIdx.x >> 5);
    int lane = threadIdx.x & 31;
    const float* hrow = g_h2 + (size_t)n * HID;
    float s1 = 0.f, s2 = 0.f;
    for (int c = lane; c < HID; c += 32) {
        float v = hrow[c];
        s1 += v * asrc[c];
        s2 += v * adst[c];
    }
    s1 = warpSum(s1); s2 = warpSum(s2);
    if (lane == 0) { g_as2[n] = s1; g_ad2[n] = s2; }
}

__global__ void edge2_kernel(const int* __restrict__ ei) {
    int e = blockIdx.x * blockDim.x + threadIdx.x;
    if (e >= ET) return;
    int s = esrc_of(ei, e), d = edst_of(ei, e);
    float v = g_as2[s] + g_ad2[d];
    g_e2[e] = v > 0.f ? v : 0.2f * v;
}

__global__ void norm2_kernel() {   // warp per node
    int n = blockIdx.x * 8 + (threadIdx.x >> 5);
    int lane = threadIdx.x & 31;
    int beg = g_off[n], end = g_off[n + 1];
    float m = -3.4e38f;
    for (int i = beg + lane; i < end; i += 32)
        m = fmaxf(m, g_e2[g_eid[i]]);
    m = warpMax(m);
    float s = 0.f;
    for (int i = beg + lane; i < end; i += 32)
        s += expf(g_e2[g_eid[i]] - m);
    s = warpSum(s);
    float inv = 1.f / s;
    for (int i = beg + lane; i < end; i += 32) {
        int e = g_eid[i];
        g_e2[e] = expf(g_e2[e] - m) * inv;
    }
}

__global__ void agg2_kernel(const float* __restrict__ b2) {
    int n = blockIdx.x;
    int t = threadIdx.x;                 // 128 threads, 4 channels each
    int c0 = t * 4;
    int beg = g_off[n], end = g_off[n + 1];
    float a0 = 0.f, a1 = 0.f, a2 = 0.f, a3 = 0.f;
    for (int i = beg; i < end; i++) {
        int e = g_eid[i], s = g_esrc[i];
        float al = g_e2[e];
        float4 v = *reinterpret_cast<const float4*>(g_h2 + (size_t)s * HID + c0);
        a0 += v.x * al; a1 += v.y * al; a2 += v.z * al; a3 += v.w * al;
    }
    float* o = g_out2 + (size_t)n * HID + c0;
    o[0] = fmaxf(a0 + b2[c0 + 0], 0.f);
    o[1] = fmaxf(a1 + b2[c0 + 1], 0.f);
    o[2] = fmaxf(a2 + b2[c0 + 2], 0.f);
    o[3] = fmaxf(a3 + b2[c0 + 3], 0.f);
}

// ---------------- launch -----------------------------------------------------
extern "C" void kernel_launch(void* const* d_in, const int* in_sizes, int n_in,
                              void* d_out, int out_size) {
    const float* x      = (const float*)d_in[0];
    const int*   ei     = (const int*)d_in[1];     // int32 view; dtype sniffed on device
    const float* W1     = (const float*)d_in[3];
    const float* a_src1 = (const float*)d_in[4];
    const float* a_dst1 = (const float*)d_in[5];
    const float* b1     = (const float*)d_in[6];
    const float* W2     = (const float*)d_in[7];
    const float* a_src2 = (const float*)d_in[8];
    const float* a_dst2 = (const float*)d_in[9];
    const float* b2     = (const float*)d_in[10];
    const float* fc1w   = (const float*)d_in[11];
    const float* fc1b   = (const float*)d_in[12];
    const float* fc2w   = (const float*)d_in[13];
    const float* fc2b   = (const float*)d_in[14];
    const float* fc3w   = (const float*)d_in[15];
    const float* fc3b   = (const float*)d_in[16];
    float* out = (float*)d_out;

    float *h1, *o1, *h2, *o2, *gg1, *gg2;
    cudaGetSymbolAddress((void**)&h1,  g_h1);
    cudaGetSymbolAddress((void**)&o1,  g_out1);
    cudaGetSymbolAddress((void**)&h2,  g_h2);
    cudaGetSymbolAddress((void**)&o2,  g_out2);
    cudaGetSymbolAddress((void**)&gg1, g_g1);
    cudaGetSymbolAddress((void**)&gg2, g_g2);

    // edge dtype + CSR (recomputed every call; deterministic work)
    detect_kernel<<<1, 32>>>(ei);
    init_kernel<<<(NN + 255) / 256, 256>>>();
    count_kernel<<<(ET + 255) / 256, 256>>>(ei);
    scan_kernel<<<1, 1024>>>();
    fill_kernel<<<(ET + 255) / 256, 256>>>(ei);

    // GAT layer 1: h1 = x @ W1 (TF32 tensor cores)
    tf32gemm<128, 128, 64, 32><<<dim3(D1 / 128, NN / 128), 256>>>(
        x, W1, nullptr, h1, NN, D1, F_IN, 0);
    alpha1_kernel<<<NN, 256>>>(a_src1, a_dst1);
    edge1_kernel<<<(ET * HEADS + 255) / 256, 256>>>(ei);
    norm1_kernel<<<NN, 256>>>();
    agg1_kernel<<<NN, 256>>>(b1);

    // GAT layer 2: h2 = out1 @ W2 (TF32 tensor cores)
    tf32gemm<128, 128, 64, 32><<<dim3(HID / 128, NN / 128), 256>>>(
        o1, W2, nullptr, h2, NN, HID, D1, 0);
    alpha2_kernel<<<NN / 8, 256>>>(a_src2, a_dst2);
    edge2_kernel<<<(ET + 255) / 256, 256>>>(ei);
    norm2_kernel<<<NN / 8, 256>>>();
    agg2_kernel<<<NN, 128>>>(b2);

    // MLP head: g = out2 viewed as [512, 4096]
    tf32gemm<64, 64, 32, 32><<<dim3(512 / 64, 512 / 64), 128>>>(
        o2, fc1w, fc1b, gg1, 512, 512, D1, 1);
    tf32gemm<64, 64, 32, 32><<<dim3(128 / 64, 512 / 64), 128>>>(
        gg1, fc2w, fc2b, gg2, 512, 128, 512, 1);
    sgemm<64, 64, 16, 4, 4><<<dim3(1, 512 / 64), 256>>>(
        gg2, fc3w, fc3b, out, 512, 10, 128, 0);
}

// round 4
// speedup vs baseline: 2.4274x; 1.0140x over previous
#include <cuda_runtime.h>
#include <cstdint>

#define NN   4096
#define NE   32768
#define ET   (NE + NN)        // edges + self loops = 36864
#define F_IN 128
#define HEADS 8
#define HID  512
#define D1   (HEADS * HID)    // 4096

// ---------------- scratch (device globals; no allocation allowed) ----------
__device__ float g_h1[(size_t)NN * D1];     // 64 MB
__device__ float g_out1[(size_t)NN * D1];   // 64 MB
__device__ float g_h2[NN * HID];            // 8 MB
__device__ float g_out2[NN * HID];          // 8 MB
__device__ float g_as1[NN * HEADS], g_ad1[NN * HEADS];
__device__ float g_e1[ET * HEADS];
__device__ float g_as2[NN], g_ad2[NN];
__device__ float g_e2[ET];
__device__ int   g_deg[NN], g_cur[NN], g_off[NN + 1];
__device__ int   g_eid[ET], g_esrc[ET];
__device__ int   g_is64;
__device__ float g_g1[512 * 512], g_g2[512 * 128];

// ---------------- helpers ---------------------------------------------------
__device__ __forceinline__ float warpSum(float v) {
    #pragma unroll
    for (int o = 16; o; o >>= 1) v += __shfl_xor_sync(0xffffffffu, v, o);
    return v;
}
__device__ __forceinline__ float warpMax(float v) {
    #pragma unroll
    for (int o = 16; o; o >>= 1) v = fmaxf(v, __shfl_xor_sync(0xffffffffu, v, o));
    return v;
}
__device__ __forceinline__ uint32_t f2tf32(float f) {
    uint32_t o;
    asm("cvt.rna.tf32.f32 %0, %1;" : "=r"(o) : "f"(f));
    return o;
}
// edge_index may be int64 or int32 depending on JAX x64 config; g_is64 set at runtime.
__device__ __forceinline__ int eload(const int* ei, int pos) {
    return g_is64 ? ei[2 * pos] : ei[pos];
}
__device__ __forceinline__ int esrc_of(const int* ei, int e) {
    return (e < NE) ? eload(ei, e) : (e - NE);
}
__device__ __forceinline__ int edst_of(const int* ei, int e) {
    return (e < NE) ? eload(ei, NE + e) : (e - NE);
}

// ---------------- dtype sniff + CSR build ----------------------------------
__global__ void detect_init_kernel(const int* __restrict__ ei) {
    int i = blockIdx.x * blockDim.x + threadIdx.x;
    if (i == 0) {
        int all0 = 1;
        for (int k = 1; k < 64; k += 2) all0 &= (ei[k] == 0);
        g_is64 = all0;   // int64: high words of small nonneg values are 0
    }
    if (i < NN) { g_deg[i] = 0; g_cur[i] = 0; }
}

__global__ void count_kernel(const int* __restrict__ ei) {
    int e = blockIdx.x * blockDim.x + threadIdx.x;
    if (e >= ET) return;
    atomicAdd(&g_deg[edst_of(ei, e)], 1);
}

__global__ void scan_kernel() {   // 1 block, 1024 threads, 4 elems/thread
    __shared__ int ws[32];
    int t = threadIdx.x, lane = t & 31, wid = t >> 5;
    int a0 = g_deg[4 * t + 0], a1 = g_deg[4 * t + 1];
    int a2 = g_deg[4 * t + 2], a3 = g_deg[4 * t + 3];
    int tsum = a0 + a1 + a2 + a3;
    int x = tsum;
    #pragma unroll
    for (int o = 1; o < 32; o <<= 1) {
        int y = __shfl_up_sync(0xffffffffu, x, o);
        if (lane >= o) x += y;
    }
    if (lane == 31) ws[wid] = x;
    __syncthreads();
    if (wid == 0) {
        int y = ws[lane];
        #pragma unroll
        for (int o = 1; o < 32; o <<= 1) {
            int z = __shfl_up_sync(0xffffffffu, y, o);
            if (lane >= o) y += z;
        }
        ws[lane] = y;
    }
    __syncthreads();
    int base = (wid ? ws[wid - 1] : 0) + (x - tsum);
    g_off[4 * t + 0] = base;
    g_off[4 * t + 1] = base + a0;
    g_off[4 * t + 2] = base + a0 + a1;
    g_off[4 * t + 3] = base + a0 + a1 + a2;
    if (t == 1023) g_off[NN] = base + tsum;
}

__global__ void fill_kernel(const int* __restrict__ ei) {
    int e = blockIdx.x * blockDim.x + threadIdx.x;
    if (e >= ET) return;
    int s = esrc_of(ei, e), d = edst_of(ei, e);
    int p = g_off[d] + atomicAdd(&g_cur[d], 1);
    g_eid[p] = e;
    g_esrc[p] = s;
}

// ---------------- TF32 tensor-core GEMM (double-buffered) --------------------
// A[M,K] rm, B[K,N] rm, C[M,N]. Requires M%BM==0, N%BN==0, K%32==0.
template<int BM, int BN, int WM, int WN>
__global__ __launch_bounds__((BM / WM) * (BN / WN) * 32)
void tf32gemm(const float* __restrict__ A, const float* __restrict__ B,
              const float* __restrict__ bias, float* __restrict__ C,
              int M, int N, int K, int relu)
{
    constexpr int BK = 32;
    constexpr int WARPS = (BM / WM) * (BN / WN);
    constexpr int THREADS = WARPS * 32;
    constexpr int MF = WM / 16, NF = WN / 8;
    constexpr int AST = BK + 4;   // A-frag LDS conflict-free
    constexpr int BST = BN + 4;   // B-frag max 2-way
    constexpr int ALD = (BM * BK) / (4 * THREADS);
    constexpr int BLD = (BK * BN) / (4 * THREADS);
    constexpr int STAGE = BM * AST + BK * BST;

    extern __shared__ uint32_t smem_dyn[];

    const int tid = threadIdx.x;
    const int wid = tid >> 5, lane = tid & 31;
    const int wm = wid / (BN / WN), wn = wid % (BN / WN);
    const int g = lane >> 2, tg = lane & 3;
    const int row0 = blockIdx.y * BM, col0 = blockIdx.x * BN;

    float acc[MF][NF][4];
    #pragma unroll
    for (int i = 0; i < MF; i++)
        #pragma unroll
        for (int j = 0; j < NF; j++)
            #pragma unroll
            for (int q = 0; q < 4; q++) acc[i][j][q] = 0.f;

    float4 pa[ALD], pb[BLD];

    auto ldAB = [&](int k0) {
        #pragma unroll
        for (int j = 0; j < ALD; j++) {
            int fid = tid + j * THREADS;
            int r = fid / (BK / 4), c4 = fid % (BK / 4);
            pa[j] = *reinterpret_cast<const float4*>(A + (size_t)(row0 + r) * K + k0 + c4 * 4);
        }
        #pragma unroll
        for (int j = 0; j < BLD; j++) {
            int fid = tid + j * THREADS;
            int r = fid / (BN / 4), c4 = fid % (BN / 4);
            pb[j] = *reinterpret_cast<const float4*>(B + (size_t)(k0 + r) * N + col0 + c4 * 4);
        }
    };
    auto stash = [&](int buf) {
        uint32_t* As = smem_dyn + buf * STAGE;
        uint32_t* Bs = As + BM * AST;
        #pragma unroll
        for (int j = 0; j < ALD; j++) {
            int fid = tid + j * THREADS;
            int r = fid / (BK / 4), c4 = fid % (BK / 4);
            uint4 v;
            v.x = f2tf32(pa[j].x); v.y = f2tf32(pa[j].y);
            v.z = f2tf32(pa[j].z); v.w = f2tf32(pa[j].w);
            *reinterpret_cast<uint4*>(&As[r * AST + c4 * 4]) = v;
        }
        #pragma unroll
        for (int j = 0; j < BLD; j++) {
            int fid = tid + j * THREADS;
            int r = fid / (BN / 4), c4 = fid % (BN / 4);
            uint4 v;
            v.x = f2tf32(pb[j].x); v.y = f2tf32(pb[j].y);
            v.z = f2tf32(pb[j].z); v.w = f2tf32(pb[j].w);
            *reinterpret_cast<uint4*>(&Bs[r * BST + c4 * 4]) = v;
        }
    };

    ldAB(0);
    stash(0);
    __syncthreads();

    const int niter = K / BK;
    for (int it = 0; it < niter; ++it) {
        const int cur = it & 1;
        if (it + 1 < niter) ldAB((it + 1) * BK);   // prefetch to regs

        const uint32_t* As = smem_dyn + cur * STAGE;
        const uint32_t* Bs = As + BM * AST;
        #pragma unroll
        for (int kk = 0; kk < 4; kk++) {
            uint32_t af[MF][4], bf[NF][2];
            #pragma unroll
            for (int mf = 0; mf < MF; mf++) {
                int r = wm * WM + mf * 16;
                af[mf][0] = As[(r + g    ) * AST + kk * 8 + tg    ];
                af[mf][1] = As[(r + g + 8) * AST + kk * 8 + tg    ];
                af[mf][2] = As[(r + g    ) * AST + kk * 8 + tg + 4];
                af[mf][3] = As[(r + g + 8) * AST + kk * 8 + tg + 4];
            }
            #pragma unroll
            for (int nf = 0; nf < NF; nf++) {
                int c = wn * WN + nf * 8 + g;
                bf[nf][0] = Bs[(kk * 8 + tg    ) * BST + c];
                bf[nf][1] = Bs[(kk * 8 + tg + 4) * BST + c];
            }
            #pragma unroll
            for (int mf = 0; mf < MF; mf++)
                #pragma unroll
                for (int nf = 0; nf < NF; nf++)
                    asm volatile(
                        "mma.sync.aligned.m16n8k8.row.col.f32.tf32.tf32.f32 "
                        "{%0,%1,%2,%3},{%4,%5,%6,%7},{%8,%9},{%0,%1,%2,%3};\n"
                        : "+f"(acc[mf][nf][0]), "+f"(acc[mf][nf][1]),
                          "+f"(acc[mf][nf][2]), "+f"(acc[mf][nf][3])
                        : "r"(af[mf][0]), "r"(af[mf][1]),
                          "r"(af[mf][2]), "r"(af[mf][3]),
                          "r"(bf[nf][0]), "r"(bf[nf][1]));
        }
        if (it + 1 < niter) {
            stash(1 - cur);     // other buffer: safe, one barrier per iter
            __syncthreads();
        }
    }

    // epilogue
    #pragma unroll
    for (int mf = 0; mf < MF; mf++) {
        int r = row0 + wm * WM + mf * 16 + g;
        #pragma unroll
        for (int nf = 0; nf < NF; nf++) {
            int c = col0 + wn * WN + nf * 8 + tg * 2;
            float b0v = bias ? bias[c] : 0.f;
            float b1v = bias ? bias[c + 1] : 0.f;
            float v0 = acc[mf][nf][0] + b0v, v1 = acc[mf][nf][1] + b1v;
            float v2 = acc[mf][nf][2] + b0v, v3 = acc[mf][nf][3] + b1v;
            if (relu) {
                v0 = fmaxf(v0, 0.f); v1 = fmaxf(v1, 0.f);
                v2 = fmaxf(v2, 0.f); v3 = fmaxf(v3, 0.f);
            }
            *reinterpret_cast<float2*>(C + (size_t)r * N + c) = make_float2(v0, v1);
            *reinterpret_cast<float2*>(C + (size_t)(r + 8) * N + c) = make_float2(v2, v3);
        }
    }
}

// ---------------- fp32 tiled SGEMM (small tail GEMM only) --------------------
template<int BM, int BN, int BK, int TM, int TN>
__global__ __launch_bounds__((BM / TM) * (BN / TN))
void sgemm(const float* __restrict__ A, const float* __restrict__ B,
           const float* __restrict__ bias, float* __restrict__ C,
           int M, int N, int K, int relu)
{
    constexpr int THREADS = (BM / TM) * (BN / TN);
    __shared__ float As[BK][BM];
    __shared__ float Bs[BK][BN];
    const int tid = threadIdx.x;
    const int row0 = blockIdx.y * BM, col0 = blockIdx.x * BN;
    const int tr = (tid / (BN / TN)) * TM;
    const int tc = (tid % (BN / TN)) * TN;
    const bool vb = (N % 4) == 0;

    float acc[TM][TN];
    #pragma unroll
    for (int i = 0; i < TM; i++)
        #pragma unroll
        for (int j = 0; j < TN; j++) acc[i][j] = 0.f;

    for (int k0 = 0; k0 < K; k0 += BK) {
        #pragma unroll 4
        for (int i = tid * 4; i < BM * BK; i += THREADS * 4) {
            int r = i / BK, c = i % BK;
            int gr = row0 + r, gc = k0 + c;
            float4 v = make_float4(0.f, 0.f, 0.f, 0.f);
            if (gr < M) v = *reinterpret_cast<const float4*>(A + (size_t)gr * K + gc);
            As[c + 0][r] = v.x; As[c + 1][r] = v.y;
            As[c + 2][r] = v.z; As[c + 3][r] = v.w;
        }
        #pragma unroll 4
        for (int i = tid * 4; i < BK * BN; i += THREADS * 4) {
            int r = i / BN, c = i % BN;
            int gr = k0 + r, gc = col0 + c;
            float vv0 = 0.f, vv1 = 0.f, vv2 = 0.f, vv3 = 0.f;
            if (vb && gc + 3 < N) {
                float4 v = *reinterpret_cast<const float4*>(B + (size_t)gr * N + gc);
                vv0 = v.x; vv1 = v.y; vv2 = v.z; vv3 = v.w;
            } else {
                if (gc + 0 < N) vv0 = B[(size_t)gr * N + gc + 0];
                if (gc + 1 < N) vv1 = B[(size_t)gr * N + gc + 1];
                if (gc + 2 < N) vv2 = B[(size_t)gr * N + gc + 2];
                if (gc + 3 < N) vv3 = B[(size_t)gr * N + gc + 3];
            }
            Bs[r][c + 0] = vv0; Bs[r][c + 1] = vv1;
            Bs[r][c + 2] = vv2; Bs[r][c + 3] = vv3;
        }
        __syncthreads();
        #pragma unroll
        for (int kk = 0; kk < BK; kk++) {
            float ar[TM], br[TN];
            #pragma unroll
            for (int i = 0; i < TM; i++) ar[i] = As[kk][tr + i];
            #pragma unroll
            for (int j = 0; j < TN; j++) br[j] = Bs[kk][tc + j];
            #pragma unroll
            for (int i = 0; i < TM; i++)
                #pragma unroll
                for (int j = 0; j < TN; j++) acc[i][j] += ar[i] * br[j];
        }
        __syncthreads();
    }
    #pragma unroll
    for (int i = 0; i < TM; i++) {
        int r = row0 + tr + i;
        if (r >= M) continue;
        #pragma unroll
        for (int j = 0; j < TN; j++) {
            int c = col0 + tc + j;
            if (c >= N) continue;
            float v = acc[i][j] + (bias ? bias[c] : 0.f);
            if (relu) v = fmaxf(v, 0.f);
            C[(size_t)r * N + c] = v;
        }
    }
}

// ---------------- GAT layer 1 (8 heads x 512) -------------------------------
__global__ void alpha1_kernel(const float* __restrict__ asrc,
                              const float* __restrict__ adst) {
    int n = blockIdx.x;
    int w = threadIdx.x >> 5, lane = threadIdx.x & 31;   // w = head
    const float* hrow = g_h1 + (size_t)n * D1 + w * HID;
    float s1 = 0.f, s2 = 0.f;
    for (int c = lane; c < HID; c += 32) {
        float v = hrow[c];
        s1 += v * asrc[w * HID + c];
        s2 += v * adst[w * HID + c];
    }
    s1 = warpSum(s1); s2 = warpSum(s2);
    if (lane == 0) { g_as1[n * HEADS + w] = s1; g_ad1[n * HEADS + w] = s2; }
}

__global__ void edge1_kernel(const int* __restrict__ ei) {
    int idx = blockIdx.x * blockDim.x + threadIdx.x;
    if (idx >= ET * HEADS) return;
    int e = idx >> 3, h = idx & 7;
    int s = esrc_of(ei, e), d = edst_of(ei, e);
    float v = g_as1[s * HEADS + h] + g_ad1[d * HEADS + h];
    g_e1[idx] = v > 0.f ? v : 0.2f * v;
}

// fused segment-softmax + weighted gather-aggregate, layer 1
#define CH1 128
__global__ __launch_bounds__(256)
void norm_agg1_kernel(const float* __restrict__ b1) {
    __shared__ float sm[HEADS], sinv[HEADS];
    __shared__ float sal[CH1 * HEADS];
    __shared__ int   ssrc[CH1];
    int n = blockIdx.x;
    int t = threadIdx.x, w = t >> 5, lane = t & 31;   // warp w handles head w
    int beg = g_off[n], end = g_off[n + 1];

    // per-head softmax stats (warp per head)
    float m = -3.4e38f;
    for (int i = beg + lane; i < end; i += 32)
        m = fmaxf(m, g_e1[g_eid[i] * HEADS + w]);
    m = warpMax(m);
    float s = 0.f;
    for (int i = beg + lane; i < end; i += 32)
        s += expf(g_e1[g_eid[i] * HEADS + w] - m);
    s = warpSum(s);
    if (lane == 0) { sm[w] = m; sinv[w] = 1.f / s; }
    __syncthreads();

    int c0 = t * 16;                 // 16 channels per thread
    int head = c0 >> 9;              // uniform per warp
    float acc[16];
    #pragma unroll
    for (int j = 0; j < 16; j++) acc[j] = 0.f;

    for (int cs = beg; cs < end; cs += CH1) {
        int cnt = min(end - cs, CH1);
        // stage alphas + src indices in smem
        for (int j = t; j < cnt * HEADS; j += 256) {
            int i = cs + (j >> 3), h = j & 7;
            sal[j] = expf(g_e1[g_eid[i] * HEADS + h] - sm[h]) * sinv[h];
        }
        for (int j = t; j < cnt; j += 256) ssrc[j] = g_esrc[cs + j];
        __syncthreads();

        #pragma unroll 2
        for (int i = 0; i < cnt; i++) {
            float al = sal[i * HEADS + head];          // warp broadcast
            const float4* hs = reinterpret_cast<const float4*>(
                g_h1 + (size_t)ssrc[i] * D1 + c0);
            #pragma unroll
            for (int j = 0; j < 4; j++) {
                float4 v = hs[j];
                acc[4 * j + 0] += v.x * al; acc[4 * j + 1] += v.y * al;
                acc[4 * j + 2] += v.z * al; acc[4 * j + 3] += v.w * al;
            }
        }
        __syncthreads();
    }
    float* o = g_out1 + (size_t)n * D1 + c0;
    #pragma unroll
    for (int j = 0; j < 16; j++)
        o[j] = fmaxf(acc[j] + b1[c0 + j], 0.f);        // relu after GAT1
}

// ---------------- GAT layer 2 (1 head x 512) --------------------------------
__global__ void alpha2_kernel(const float* __restrict__ asrc,
                              const float* __restrict__ adst) {
    int n = blockIdx.x * 8 + (threadIdx.x >> 5);
    int lane = threadIdx.x & 31;
    const float* hrow = g_h2 + (size_t)n * HID;
    float s1 = 0.f, s2 = 0.f;
    for (int c = lane; c < HID; c += 32) {
        float v = hrow[c];
        s1 += v * asrc[c];
        s2 += v * adst[c];
    }
    s1 = warpSum(s1); s2 = warpSum(s2);
    if (lane == 0) { g_as2[n] = s1; g_ad2[n] = s2; }
}

__global__ void edge2_kernel(const int* __restrict__ ei) {
    int e = blockIdx.x * blockDim.x + threadIdx.x;
    if (e >= ET) return;
    int s = esrc_of(ei, e), d = edst_of(ei, e);
    float v = g_as2[s] + g_ad2[d];
    g_e2[e] = v > 0.f ? v : 0.2f * v;
}

// fused segment-softmax + aggregate, layer 2 (128 threads/node)
#define CH2 256
__global__ __launch_bounds__(128)
void norm_agg2_kernel(const float* __restrict__ b2) {
    __shared__ float sred[4];
    __shared__ float sal[CH2];
    __shared__ int   ssrc[CH2];
    int n = blockIdx.x;
    int t = threadIdx.x, w = t >> 5, lane = t & 31;
    int beg = g_off[n], end = g_off[n + 1];

    float m = -3.4e38f;
    for (int i = beg + t; i < end; i += 128)
        m = fmaxf(m, g_e2[g_eid[i]]);
    m = warpMax(m);
    if (lane == 0) sred[w] = m;
    __syncthreads();
    m = fmaxf(fmaxf(sred[0], sred[1]), fmaxf(sred[2], sred[3]));
    __syncthreads();
    float s = 0.f;
    for (int i = beg + t; i < end; i += 128)
        s += expf(g_e2[g_eid[i]] - m);
    s = warpSum(s);
    if (lane == 0) sred[w] = s;
    __syncthreads();
    float inv = 1.f / (sred[0] + sred[1] + sred[2] + sred[3]);

    int c0 = t * 4;
    float a0 = 0.f, a1 = 0.f, a2 = 0.f, a3 = 0.f;
    for (int cs = beg; cs < end; cs += CH2) {
        int cnt = min(end - cs, CH2);
        __syncthreads();
        for (int j = t; j < cnt; j += 128) {
            sal[j] = expf(g_e2[g_eid[cs + j]] - m) * inv;
            ssrc[j] = g_esrc[cs + j];
        }
        __syncthreads();
        #pragma unroll 2
        for (int i = 0; i < cnt; i++) {
            float al = sal[i];
            float4 v = *reinterpret_cast<const float4*>(
                g_h2 + (size_t)ssrc[i] * HID + c0);
            a0 += v.x * al; a1 += v.y * al; a2 += v.z * al; a3 += v.w * al;
        }
    }
    float* o = g_out2 + (size_t)n * HID + c0;
    o[0] = fmaxf(a0 + b2[c0 + 0], 0.f);
    o[1] = fmaxf(a1 + b2[c0 + 1], 0.f);
    o[2] = fmaxf(a2 + b2[c0 + 2], 0.f);
    o[3] = fmaxf(a3 + b2[c0 + 3], 0.f);
}

// ---------------- launch -----------------------------------------------------
static inline int smem_bytes(int BM, int BN) {
    return 2 * (BM * 36 + 32 * (BN + 4)) * 4;
}

extern "C" void kernel_launch(void* const* d_in, const int* in_sizes, int n_in,
                              void* d_out, int out_size) {
    const float* x      = (const float*)d_in[0];
    const int*   ei     = (const int*)d_in[1];     // int32 view; dtype sniffed on device
    const float* W1     = (const float*)d_in[3];
    const float* a_src1 = (const float*)d_in[4];
    const float* a_dst1 = (const float*)d_in[5];
    const float* b1     = (const float*)d_in[6];
    const float* W2     = (const float*)d_in[7];
    const float* a_src2 = (const float*)d_in[8];
    const float* a_dst2 = (const float*)d_in[9];
    const float* b2     = (const float*)d_in[10];
    const float* fc1w   = (const float*)d_in[11];
    const float* fc1b   = (const float*)d_in[12];
    const float* fc2w   = (const float*)d_in[13];
    const float* fc2b   = (const float*)d_in[14];
    const float* fc3w   = (const float*)d_in[15];
    const float* fc3b   = (const float*)d_in[16];
    float* out = (float*)d_out;

    float *h1, *o1, *h2, *o2, *gg1, *gg2;
    cudaGetSymbolAddress((void**)&h1,  g_h1);
    cudaGetSymbolAddress((void**)&o1,  g_out1);
    cudaGetSymbolAddress((void**)&h2,  g_h2);
    cudaGetSymbolAddress((void**)&o2,  g_out2);
    cudaGetSymbolAddress((void**)&gg1, g_g1);
    cudaGetSymbolAddress((void**)&gg2, g_g2);

    const int SM_BIG   = smem_bytes(128, 128);   // 70656 B
    const int SM_SMALL = smem_bytes(64, 64);     // 35840 B
    cudaFuncSetAttribute(tf32gemm<128, 128, 64, 32>,
                         cudaFuncAttributeMaxDynamicSharedMemorySize, SM_BIG);
    cudaFuncSetAttribute(tf32gemm<64, 64, 32, 32>,
                         cudaFuncAttributeMaxDynamicSharedMemorySize, SM_SMALL);

    // edge dtype + CSR (recomputed every call; deterministic work)
    detect_init_kernel<<<(NN + 255) / 256, 256>>>(ei);
    count_kernel<<<(ET + 255) / 256, 256>>>(ei);
    scan_kernel<<<1, 1024>>>();
    fill_kernel<<<(ET + 255) / 256, 256>>>(ei);

    // GAT layer 1: h1 = x @ W1 (TF32 tensor cores)
    tf32gemm<128, 128, 64, 32><<<dim3(D1 / 128, NN / 128), 256, SM_BIG>>>(
        x, W1, nullptr, h1, NN, D1, F_IN, 0);
    alpha1_kernel<<<NN, 256>>>(a_src1, a_dst1);
    edge1_kernel<<<(ET * HEADS + 255) / 256, 256>>>(ei);
    norm_agg1_kernel<<<NN, 256>>>(b1);

    // GAT layer 2: h2 = out1 @ W2 (TF32 tensor cores)
    tf32gemm<128, 128, 64, 32><<<dim3(HID / 128, NN / 128), 256, SM_BIG>>>(
        o1, W2, nullptr, h2, NN, HID, D1, 0);
    alpha2_kernel<<<NN / 8, 256>>>(a_src2, a_dst2);
    edge2_kernel<<<(ET + 255) / 256, 256>>>(ei);
    norm_agg2_kernel<<<NN, 128>>>(b2);

    // MLP head: g = out2 viewed as [512, 4096]
    tf32gemm<64, 64, 32, 32><<<dim3(512 / 64, 512 / 64), 128, SM_SMALL>>>(
        o2, fc1w, fc1b, gg1, 512, 512, D1, 1);
    tf32gemm<64, 64, 32, 32><<<dim3(128 / 64, 512 / 64), 128, SM_SMALL>>>(
        gg1, fc2w, fc2b, gg2, 512, 128, 512, 1);
    sgemm<64, 64, 16, 4, 4><<<dim3(1, 512 / 64), 256>>>(
        gg2, fc3w, fc3b, out, 512, 10, 128, 0);
}

// round 7
// speedup vs baseline: 2.4489x; 1.0089x over previous
#include <cuda_runtime.h>
#include <cstdint>

#define NN   4096
#define NE   32768
#define ET   (NE + NN)        // edges + self loops = 36864
#define F_IN 128
#define HEADS 8
#define HID  512
#define D1   (HEADS * HID)    // 4096

// ---------------- scratch (device globals; no allocation allowed) ----------
__device__ float g_h1[(size_t)NN * D1];     // 64 MB
__device__ float g_out1[(size_t)NN * D1];   // 64 MB
__device__ float g_h2[NN * HID];            // 8 MB
__device__ float g_out2[NN * HID];          // 8 MB
__device__ float g_wa1[F_IN * 16];          // W1 @ [a_src;a_dst] projections
__device__ float g_as1[NN * HEADS], g_ad1[NN * HEADS];
__device__ float g_as2[NN], g_ad2[NN];
__device__ int   g_deg[NN], g_cur[NN], g_off[NN + 1];
__device__ int   g_esrc[ET];
__device__ int   g_is64;
__device__ float g_g1[512 * 512], g_g2[512 * 128];

// ---------------- helpers ---------------------------------------------------
__device__ __forceinline__ float warpSum(float v) {
    #pragma unroll
    for (int o = 16; o; o >>= 1) v += __shfl_xor_sync(0xffffffffu, v, o);
    return v;
}
__device__ __forceinline__ float warpMax(float v) {
    #pragma unroll
    for (int o = 16; o; o >>= 1) v = fmaxf(v, __shfl_xor_sync(0xffffffffu, v, o));
    return v;
}
__device__ __forceinline__ uint32_t f2tf32(float f) {
    uint32_t o;
    asm("cvt.rna.tf32.f32 %0, %1;" : "=r"(o) : "f"(f));
    return o;
}
__device__ __forceinline__ float lrelu(float v) {
    return v > 0.f ? v : 0.2f * v;
}
// edge_index may be int64 or int32 depending on JAX x64 config; g_is64 set at runtime.
__device__ __forceinline__ int eload(const int* ei, int pos) {
    return g_is64 ? ei[2 * pos] : ei[pos];
}
__device__ __forceinline__ int esrc_of(const int* ei, int e) {
    return (e < NE) ? eload(ei, e) : (e - NE);
}
__device__ __forceinline__ int edst_of(const int* ei, int e) {
    return (e < NE) ? eload(ei, NE + e) : (e - NE);
}

// ---------------- dtype sniff + CSR build ----------------------------------
__global__ void detect_init_kernel(const int* __restrict__ ei) {
    int i = blockIdx.x * blockDim.x + threadIdx.x;
    if (i == 0) {
        int all0 = 1;
        for (int k = 1; k < 64; k += 2) all0 &= (ei[k] == 0);
        g_is64 = all0;
    }
    if (i < NN) { g_deg[i] = 0; g_cur[i] = 0; }
}

__global__ void count_kernel(const int* __restrict__ ei) {
    int e = blockIdx.x * blockDim.x + threadIdx.x;
    if (e >= ET) return;
    atomicAdd(&g_deg[edst_of(ei, e)], 1);
}

__global__ void scan_kernel() {
    __shared__ int ws[32];
    int t = threadIdx.x, lane = t & 31, wid = t >> 5;
    int a0 = g_deg[4 * t + 0], a1 = g_deg[4 * t + 1];
    int a2 = g_deg[4 * t + 2], a3 = g_deg[4 * t + 3];
    int tsum = a0 + a1 + a2 + a3;
    int x = tsum;
    #pragma unroll
    for (int o = 1; o < 32; o <<= 1) {
        int y = __shfl_up_sync(0xffffffffu, x, o);
        if (lane >= o) x += y;
    }
    if (lane == 31) ws[wid] = x;
    __syncthreads();
    if (wid == 0) {
        int y = ws[lane];
        #pragma unroll
        for (int o = 1; o < 32; o <<= 1) {
            int z = __shfl_up_sync(0xffffffffu, y, o);
            if (lane >= o) y += z;
        }
        ws[lane] = y;
    }
    __syncthreads();
    int base = (wid ? ws[wid - 1] : 0) + (x - tsum);
    g_off[4 * t + 0] = base;
    g_off[4 * t + 1] = base + a0;
    g_off[4 * t + 2] = base + a0 + a1;
    g_off[4 * t + 3] = base + a0 + a1 + a2;
    if (t == 1023) g_off[NN] = base + tsum;
}

__global__ void fill_kernel(const int* __restrict__ ei) {
    int e = blockIdx.x * blockDim.x + threadIdx.x;
    if (e >= ET) return;
    int s = esrc_of(ei, e), d = edst_of(ei, e);
    int p = g_off[d] + atomicAdd(&g_cur[d], 1);
    g_esrc[p] = s;
}

// ---------------- TF32 tensor-core GEMM (mma.sync, double-buffered) ----------
// A[M,K] rm, B[K,N] rm, C[M,N]. Requires M%BM==0, N%BN==0, K%32==0.
template<int BM, int BN, int WM, int WN>
__global__ __launch_bounds__((BM / WM) * (BN / WN) * 32)
void tf32gemm(const float* __restrict__ A, const float* __restrict__ B,
              const float* __restrict__ bias, float* __restrict__ C,
              int M, int N, int K, int relu)
{
    constexpr int BK = 32;
    constexpr int WARPS = (BM / WM) * (BN / WN);
    constexpr int THREADS = WARPS * 32;
    constexpr int MF = WM / 16, NF = WN / 8;
    constexpr int AST = BK + 4;   // A-frag LDS conflict-free
    constexpr int BST = BN + 4;   // B-frag max 2-way
    constexpr int ALD = (BM * BK) / (4 * THREADS);
    constexpr int BLD = (BK * BN) / (4 * THREADS);
    constexpr int STAGE = BM * AST + BK * BST;

    extern __shared__ uint32_t smem_dyn[];
    const int tid = threadIdx.x;
    const int wid = tid >> 5, lane = tid & 31;
    const int wm = wid / (BN / WN), wn = wid % (BN / WN);
    const int g = lane >> 2, tg = lane & 3;
    const int row0 = blockIdx.y * BM, col0 = blockIdx.x * BN;

    float acc[MF][NF][4];
    #pragma unroll
    for (int i = 0; i < MF; i++)
        #pragma unroll
        for (int j = 0; j < NF; j++)
            #pragma unroll
            for (int q = 0; q < 4; q++) acc[i][j][q] = 0.f;

    float4 pa[ALD], pb[BLD];
    auto ldAB = [&](int k0) {
        #pragma unroll
        for (int j = 0; j < ALD; j++) {
            int fid = tid + j * THREADS;
            int r = fid / (BK / 4), c4 = fid % (BK / 4);
            pa[j] = *reinterpret_cast<const float4*>(A + (size_t)(row0 + r) * K + k0 + c4 * 4);
        }
        #pragma unroll
        for (int j = 0; j < BLD; j++) {
            int fid = tid + j * THREADS;
            int r = fid / (BN / 4), c4 = fid % (BN / 4);
            pb[j] = *reinterpret_cast<const float4*>(B + (size_t)(k0 + r) * N + col0 + c4 * 4);
        }
    };
    auto stash = [&](int buf) {
        uint32_t* As = smem_dyn + buf * STAGE;
        uint32_t* Bs = As + BM * AST;
        #pragma unroll
        for (int j = 0; j < ALD; j++) {
            int fid = tid + j * THREADS;
            int r = fid / (BK / 4), c4 = fid % (BK / 4);
            uint4 v;
            v.x = f2tf32(pa[j].x); v.y = f2tf32(pa[j].y);
            v.z = f2tf32(pa[j].z); v.w = f2tf32(pa[j].w);
            *reinterpret_cast<uint4*>(&As[r * AST + c4 * 4]) = v;
        }
        #pragma unroll
        for (int j = 0; j < BLD; j++) {
            int fid = tid + j * THREADS;
            int r = fid / (BN / 4), c4 = fid % (BN / 4);
            uint4 v;
            v.x = f2tf32(pb[j].x); v.y = f2tf32(pb[j].y);
            v.z = f2tf32(pb[j].z); v.w = f2tf32(pb[j].w);
            *reinterpret_cast<uint4*>(&Bs[r * BST + c4 * 4]) = v;
        }
    };

    ldAB(0);
    stash(0);
    __syncthreads();

    const int niter = K / BK;
    for (int it = 0; it < niter; ++it) {
        const int cur = it & 1;
        if (it + 1 < niter) ldAB((it + 1) * BK);
        const uint32_t* As = smem_dyn + cur * STAGE;
        const uint32_t* Bs = As + BM * AST;
        #pragma unroll
        for (int kk = 0; kk < 4; kk++) {
            uint32_t af[MF][4], bf[NF][2];
            #pragma unroll
            for (int mf = 0; mf < MF; mf++) {
                int r = wm * WM + mf * 16;
                af[mf][0] = As[(r + g    ) * AST + kk * 8 + tg    ];
                af[mf][1] = As[(r + g + 8) * AST + kk * 8 + tg    ];
                af[mf][2] = As[(r + g    ) * AST + kk * 8 + tg + 4];
                af[mf][3] = As[(r + g + 8) * AST + kk * 8 + tg + 4];
            }
            #pragma unroll
            for (int nf = 0; nf < NF; nf++) {
                int c = wn * WN + nf * 8 + g;
                bf[nf][0] = Bs[(kk * 8 + tg    ) * BST + c];
                bf[nf][1] = Bs[(kk * 8 + tg + 4) * BST + c];
            }
            #pragma unroll
            for (int mf = 0; mf < MF; mf++)
                #pragma unroll
                for (int nf = 0; nf < NF; nf++)
                    asm volatile(
                        "mma.sync.aligned.m16n8k8.row.col.f32.tf32.tf32.f32 "
                        "{%0,%1,%2,%3},{%4,%5,%6,%7},{%8,%9},{%0,%1,%2,%3};\n"
                        : "+f"(acc[mf][nf][0]), "+f"(acc[mf][nf][1]),
                          "+f"(acc[mf][nf][2]), "+f"(acc[mf][nf][3])
                        : "r"(af[mf][0]), "r"(af[mf][1]),
                          "r"(af[mf][2]), "r"(af[mf][3]),
                          "r"(bf[nf][0]), "r"(bf[nf][1]));
        }
        if (it + 1 < niter) {
            stash(1 - cur);
            __syncthreads();
        }
    }
    #pragma unroll
    for (int mf = 0; mf < MF; mf++) {
        int r = row0 + wm * WM + mf * 16 + g;
        #pragma unroll
        for (int nf = 0; nf < NF; nf++) {
            int c = col0 + wn * WN + nf * 8 + tg * 2;
            float b0v = bias ? bias[c] : 0.f;
            float b1v = bias ? bias[c + 1] : 0.f;
            float v0 = acc[mf][nf][0] + b0v, v1 = acc[mf][nf][1] + b1v;
            float v2 = acc[mf][nf][2] + b0v, v3 = acc[mf][nf][3] + b1v;
            if (relu) {
                v0 = fmaxf(v0, 0.f); v1 = fmaxf(v1, 0.f);
                v2 = fmaxf(v2, 0.f); v3 = fmaxf(v3, 0.f);
            }
            *reinterpret_cast<float2*>(C + (size_t)r * N + c) = make_float2(v0, v1);
            *reinterpret_cast<float2*>(C + (size_t)(r + 8) * N + c) = make_float2(v2, v3);
        }
    }
}

// ---------------- fp32 tiled SGEMM (tail GEMM only) --------------------------
template<int BM, int BN, int BK, int TM, int TN>
__global__ __launch_bounds__((BM / TM) * (BN / TN))
void sgemm(const float* __restrict__ A, const float* __restrict__ B,
           const float* __restrict__ bias, float* __restrict__ C,
           int M, int N, int K, int relu)
{
    constexpr int THREADS = (BM / TM) * (BN / TN);
    __shared__ float As[BK][BM];
    __shared__ float Bs[BK][BN];
    const int tid = threadIdx.x;
    const int row0 = blockIdx.y * BM, col0 = blockIdx.x * BN;
    const int tr = (tid / (BN / TN)) * TM;
    const int tc = (tid % (BN / TN)) * TN;
    const bool vb = (N % 4) == 0;

    float acc[TM][TN];
    #pragma unroll
    for (int i = 0; i < TM; i++)
        #pragma unroll
        for (int j = 0; j < TN; j++) acc[i][j] = 0.f;

    for (int k0 = 0; k0 < K; k0 += BK) {
        #pragma unroll 4
        for (int i = tid * 4; i < BM * BK; i += THREADS * 4) {
            int r = i / BK, c = i % BK;
            int gr = row0 + r, gc = k0 + c;
            float4 v = make_float4(0.f, 0.f, 0.f, 0.f);
            if (gr < M) v = *reinterpret_cast<const float4*>(A + (size_t)gr * K + gc);
            As[c + 0][r] = v.x; As[c + 1][r] = v.y;
            As[c + 2][r] = v.z; As[c + 3][r] = v.w;
        }
        #pragma unroll 4
        for (int i = tid * 4; i < BK * BN; i += THREADS * 4) {
            int r = i / BN, c = i % BN;
            int gr = k0 + r, gc = col0 + c;
            float vv0 = 0.f, vv1 = 0.f, vv2 = 0.f, vv3 = 0.f;
            if (vb && gc + 3 < N) {
                float4 v = *reinterpret_cast<const float4*>(B + (size_t)gr * N + gc);
                vv0 = v.x; vv1 = v.y; vv2 = v.z; vv3 = v.w;
            } else {
                if (gc + 0 < N) vv0 = B[(size_t)gr * N + gc + 0];
                if (gc + 1 < N) vv1 = B[(size_t)gr * N + gc + 1];
                if (gc + 2 < N) vv2 = B[(size_t)gr * N + gc + 2];
                if (gc + 3 < N) vv3 = B[(size_t)gr * N + gc + 3];
            }
            Bs[r][c + 0] = vv0; Bs[r][c + 1] = vv1;
            Bs[r][c + 2] = vv2; Bs[r][c + 3] = vv3;
        }
        __syncthreads();
        #pragma unroll
        for (int kk = 0; kk < BK; kk++) {
            float ar[TM], br[TN];
            #pragma unroll
            for (int i = 0; i < TM; i++) ar[i] = As[kk][tr + i];
            #pragma unroll
            for (int j = 0; j < TN; j++) br[j] = Bs[kk][tc + j];
            #pragma unroll
            for (int i = 0; i < TM; i++)
                #pragma unroll
                for (int j = 0; j < TN; j++) acc[i][j] += ar[i] * br[j];
        }
        __syncthreads();
    }
    #pragma unroll
    for (int i = 0; i < TM; i++) {
        int r = row0 + tr + i;
        if (r >= M) continue;
        #pragma unroll
        for (int j = 0; j < TN; j++) {
            int c = col0 + tc + j;
            if (c >= N) continue;
            float v = acc[i][j] + (bias ? bias[c] : 0.f);
            if (relu) v = fmaxf(v, 0.f);
            C[(size_t)r * N + c] = v;
        }
    }
}

// ---------------- GAT layer 1 -------------------------------------------------
// wa[f][o] = sum_c W1[f][h*512+c] * a[h][c], o in [0,16): 0-7 src, 8-15 dst
__global__ void prep_wa1_kernel(const float* __restrict__ W1,
                                const float* __restrict__ a1s,
                                const float* __restrict__ a1d) {
    int f = blockIdx.x;
    int w = threadIdx.x >> 5, lane = threadIdx.x & 31;   // 16 warps
    int h = w & 7;
    const float* a = (w < 8) ? a1s : a1d;
    float s = 0.f;
    for (int c = lane; c < HID; c += 32)
        s += W1[(size_t)f * D1 + h * HID + c] * a[h * HID + c];
    s = warpSum(s);
    if (lane == 0) g_wa1[f * 16 + w] = s;
}

// alpha_src/dst[n][h] = x[n,:] @ wa1[:, h]   (exact linear-algebra fusion)
__global__ void alpha1_fast_kernel(const float* __restrict__ x) {
    int n = blockIdx.x * 8 + (threadIdx.x >> 5);
    int lane = threadIdx.x & 31;
    float xv[4];
    #pragma unroll
    for (int j = 0; j < 4; j++) xv[j] = x[(size_t)n * F_IN + lane + 32 * j];
    #pragma unroll
    for (int o = 0; o < 16; o++) {
        float s = 0.f;
        #pragma unroll
        for (int j = 0; j < 4; j++) s += xv[j] * g_wa1[(lane + 32 * j) * 16 + o];
        s = warpSum(s);
        if (lane == 0) {
            if (o < 8) g_as1[n * 8 + o] = s;
            else       g_ad1[n * 8 + (o - 8)] = s;
        }
    }
}

// fused leaky-relu logits + segment-softmax + weighted gather-aggregate (L1)
#define CH1 128
__global__ __launch_bounds__(256)
void norm_agg1_kernel(const float* __restrict__ b1) {
    __shared__ float sm[HEADS], sinv[HEADS], sadn[HEADS];
    __shared__ float sal[CH1 * HEADS];
    __shared__ int   ssrc[CH1];
    int n = blockIdx.x;
    int t = threadIdx.x, w = t >> 5, lane = t & 31;   // warp w = head w
    int beg = g_off[n], end = g_off[n + 1];

    float adn = g_ad1[n * HEADS + w];
    if (lane == 0) sadn[w] = adn;
    // per-head softmax stats; logits recomputed on the fly
    float m = -3.4e38f;
    for (int i = beg + lane; i < end; i += 32)
        m = fmaxf(m, lrelu(g_as1[g_esrc[i] * HEADS + w] + adn));
    m = warpMax(m);
    float s = 0.f;
    for (int i = beg + lane; i < end; i += 32)
        s += expf(lrelu(g_as1[g_esrc[i] * HEADS + w] + adn) - m);
    s = warpSum(s);
    if (lane == 0) { sm[w] = m; sinv[w] = 1.f / s; }
    __syncthreads();

    int c0 = t * 16;
    int head = c0 >> 9;
    float acc[16];
    #pragma unroll
    for (int j = 0; j < 16; j++) acc[j] = 0.f;

    for (int cs = beg; cs < end; cs += CH1) {
        int cnt = min(end - cs, CH1);
        for (int j = t; j < cnt; j += 256) ssrc[j] = g_esrc[cs + j];
        __syncthreads();
        for (int j = t; j < cnt * HEADS; j += 256) {
            int i = j >> 3, h = j & 7;
            float v = lrelu(g_as1[ssrc[i] * HEADS + h] + sadn[h]);
            sal[j] = expf(v - sm[h]) * sinv[h];
        }
        __syncthreads();
        #pragma unroll 2
        for (int i = 0; i < cnt; i++) {
            float al = sal[i * HEADS + head];
            const float4* hs = reinterpret_cast<const float4*>(
                g_h1 + (size_t)ssrc[i] * D1 + c0);
            #pragma unroll
            for (int j = 0; j < 4; j++) {
                float4 v = hs[j];
                acc[4 * j + 0] += v.x * al; acc[4 * j + 1] += v.y * al;
                acc[4 * j + 2] += v.z * al; acc[4 * j + 3] += v.w * al;
            }
        }
        __syncthreads();
    }
    float* o = g_out1 + (size_t)n * D1 + c0;
    #pragma unroll
    for (int j = 0; j < 16; j++)
        o[j] = fmaxf(acc[j] + b1[c0 + j], 0.f);        // relu after GAT1
}

// ---------------- GAT layer 2 -------------------------------------------------
__global__ void alpha2_kernel(const float* __restrict__ asrc,
                              const float* __restrict__ adst) {
    int n = blockIdx.x * 8 + (threadIdx.x >> 5);
    int lane = threadIdx.x & 31;
    const float* hrow = g_h2 + (size_t)n * HID;
    float s1 = 0.f, s2 = 0.f;
    for (int c = lane; c < HID; c += 32) {
        float v = hrow[c];
        s1 += v * asrc[c];
        s2 += v * adst[c];
    }
    s1 = warpSum(s1); s2 = warpSum(s2);
    if (lane == 0) { g_as2[n] = s1; g_ad2[n] = s2; }
}

// fused leaky-relu logits + segment-softmax + aggregate (L2)
#define CH2 256
__global__ __launch_bounds__(128)
void norm_agg2_kernel(const float* __restrict__ b2) {
    __shared__ float sred[4];
    __shared__ float sal[CH2];
    __shared__ int   ssrc[CH2];
    int n = blockIdx.x;
    int t = threadIdx.x, w = t >> 5, lane = t & 31;
    int beg = g_off[n], end = g_off[n + 1];
    float adn = g_ad2[n];

    float m = -3.4e38f;
    for (int i = beg + t; i < end; i += 128)
        m = fmaxf(m, lrelu(g_as2[g_esrc[i]] + adn));
    m = warpMax(m);
    if (lane == 0) sred[w] = m;
    __syncthreads();
    m = fmaxf(fmaxf(sred[0], sred[1]), fmaxf(sred[2], sred[3]));
    __syncthreads();
    float s = 0.f;
    for (int i = beg + t; i < end; i += 128)
        s += expf(lrelu(g_as2[g_esrc[i]] + adn) - m);
    s = warpSum(s);
    if (lane == 0) sred[w] = s;
    __syncthreads();
    float inv = 1.f / (sred[0] + sred[1] + sred[2] + sred[3]);

    int c0 = t * 4;
    float a0 = 0.f, a1 = 0.f, a2 = 0.f, a3 = 0.f;
    for (int cs = beg; cs < end; cs += CH2) {
        int cnt = min(end - cs, CH2);
        __syncthreads();
        for (int j = t; j < cnt; j += 128) {
            int sc = g_esrc[cs + j];
            ssrc[j] = sc;
            sal[j] = expf(lrelu(g_as2[sc] + adn) - m) * inv;
        }
        __syncthreads();
        #pragma unroll 2
        for (int i = 0; i < cnt; i++) {
            float al = sal[i];
            float4 v = *reinterpret_cast<const float4*>(
                g_h2 + (size_t)ssrc[i] * HID + c0);
            a0 += v.x * al; a1 += v.y * al; a2 += v.z * al; a3 += v.w * al;
        }
    }
    float* o = g_out2 + (size_t)n * HID + c0;
    o[0] = fmaxf(a0 + b2[c0 + 0], 0.f);
    o[1] = fmaxf(a1 + b2[c0 + 1], 0.f);
    o[2] = fmaxf(a2 + b2[c0 + 2], 0.f);
    o[3] = fmaxf(a3 + b2[c0 + 3], 0.f);
}

// ---------------- launch -----------------------------------------------------
static inline int smem_bytes(int BM, int BN) {
    return 2 * (BM * 36 + 32 * (BN + 4)) * 4;
}

extern "C" void kernel_launch(void* const* d_in, const int* in_sizes, int n_in,
                              void* d_out, int out_size) {
    const float* x      = (const float*)d_in[0];
    const int*   ei     = (const int*)d_in[1];
    const float* W1     = (const float*)d_in[3];
    const float* a_src1 = (const float*)d_in[4];
    const float* a_dst1 = (const float*)d_in[5];
    const float* b1     = (const float*)d_in[6];
    const float* W2     = (const float*)d_in[7];
    const float* a_src2 = (const float*)d_in[8];
    const float* a_dst2 = (const float*)d_in[9];
    const float* b2     = (const float*)d_in[10];
    const float* fc1w   = (const float*)d_in[11];
    const float* fc1b   = (const float*)d_in[12];
    const float* fc2w   = (const float*)d_in[13];
    const float* fc2b   = (const float*)d_in[14];
    const float* fc3w   = (const float*)d_in[15];
    const float* fc3b   = (const float*)d_in[16];
    float* out = (float*)d_out;

    float *h1, *o1, *h2, *o2, *gg1, *gg2;
    cudaGetSymbolAddress((void**)&h1,  g_h1);
    cudaGetSymbolAddress((void**)&o1,  g_out1);
    cudaGetSymbolAddress((void**)&h2,  g_h2);
    cudaGetSymbolAddress((void**)&o2,  g_out2);
    cudaGetSymbolAddress((void**)&gg1, g_g1);
    cudaGetSymbolAddress((void**)&gg2, g_g2);

    const int SM_BIG   = smem_bytes(128, 128);   // 70656 B
    const int SM_SMALL = smem_bytes(64, 64);     // 35840 B
    cudaFuncSetAttribute(tf32gemm<128, 128, 64, 32>,
                         cudaFuncAttributeMaxDynamicSharedMemorySize, SM_BIG);
    cudaFuncSetAttribute(tf32gemm<64, 64, 32, 32>,
                         cudaFuncAttributeMaxDynamicSharedMemorySize, SM_SMALL);

    // alpha1 projection (input-only deps)
    prep_wa1_kernel<<<F_IN, 512>>>(W1, a_src1, a_dst1);
    alpha1_fast_kernel<<<NN / 8, 256>>>(x);

    // edge dtype + CSR
    detect_init_kernel<<<(NN + 255) / 256, 256>>>(ei);
    count_kernel<<<(ET + 255) / 256, 256>>>(ei);
    scan_kernel<<<1, 1024>>>();
    fill_kernel<<<(ET + 255) / 256, 256>>>(ei);

    // GAT layer 1: h1 = x @ W1 (TF32 tensor cores)
    tf32gemm<128, 128, 64, 32><<<dim3(D1 / 128, NN / 128), 256, SM_BIG>>>(
        x, W1, nullptr, h1, NN, D1, F_IN, 0);
    norm_agg1_kernel<<<NN, 256>>>(b1);

    // GAT layer 2: h2 = out1 @ W2 (TF32 tensor cores)
    tf32gemm<128, 128, 64, 32><<<dim3(HID / 128, NN / 128), 256, SM_BIG>>>(
        o1, W2, nullptr, h2, NN, HID, D1, 0);
    alpha2_kernel<<<NN / 8, 256>>>(a_src2, a_dst2);
    norm_agg2_kernel<<<NN, 128>>>(b2);

    // MLP head: g = out2 viewed as [512, 4096]
    tf32gemm<64, 64, 32, 32><<<dim3(512 / 64, 512 / 64), 128, SM_SMALL>>>(
        o2, fc1w, fc1b, gg1, 512, 512, D1, 1);
    tf32gemm<64, 64, 32, 32><<<dim3(128 / 64, 512 / 64), 128, SM_SMALL>>>(
        gg1, fc2w, fc2b, gg2, 512, 128, 512, 1);
    sgemm<64, 64, 16, 4, 4><<<dim3(1, 512 / 64), 256>>>(
        gg2, fc3w, fc3b, out, 512, 10, 128, 0);
}